// round 7
// baseline (speedup 1.0000x reference)
#include <cuda_runtime.h>
#include <cstdint>

#define BB 32
#define SS 512
#define HH 256
#define NB 256
#define TT 4096   // MAX_LEN

#define NTOK   (BB * SS)        // 16384 tokens
#define TPB    8                // tokens (warps) per 256-thread block
#define NTB    (NTOK / TPB)     // 2048 token blocks (64 per batch)

#define ZF     32               // frames per zerofill block (8 warps x 4)
#define NZB    (BB * (TT / ZF)) // 4096 zerofill blocks

// 256-bit streaming store (sm_100+/PTX 8.6+): 8 x b32 in one STG.256
__device__ __forceinline__ void stcs_v8(float* p, float4 a, float4 b) {
    asm volatile(
        "st.global.cs.v8.b32 [%0], {%1,%2,%3,%4,%5,%6,%7,%8};"
        :: "l"(p),
           "r"(__float_as_uint(a.x)), "r"(__float_as_uint(a.y)),
           "r"(__float_as_uint(a.z)), "r"(__float_as_uint(a.w)),
           "r"(__float_as_uint(b.x)), "r"(__float_as_uint(b.y)),
           "r"(__float_as_uint(b.z)), "r"(__float_as_uint(b.w))
        : "memory");
}

// searchsorted(linspace(vmin,vmax,NB), v, side='left'), clip [0, NB-1].
// Post-clip v <= b[NB-1] so answer in [0, NB-1]: 8 exact iterations.
__device__ __forceinline__ int quantize_bin(float v, float vmin, float vmax) {
    v = fminf(fmaxf(v, vmin), vmax);
    float step = __fdiv_rn(__fsub_rn(vmax, vmin), (float)(NB - 1));
    int lo = 0, hi = NB - 1;
    #pragma unroll
    for (int it = 0; it < 8; ++it) {
        int mid = (lo + hi) >> 1;
        float b = __fadd_rn(__fmul_rn((float)mid, step), vmin);
        if (b >= v) hi = mid; else lo = mid + 1;
    }
    return lo;
}

__device__ __forceinline__ int clamped_dur(const float* __restrict__ dur, int i) {
    return max((int)rintf(__ldg(dur + i)), 1);   // jnp.round = half-to-even
}

// Single fused kernel, 256 threads/block (8 warps).
//   blockIdx.x <  NTB : 8 tokens (one per warp) of one batch. Block scans its
//                       batch's duration row locally, then scatters with
//                       256-bit streaming stores (lane owns 32B of the row).
//   blockIdx.x >= NTB : 32 frames of one batch; zero frames >= total.
__global__ void __launch_bounds__(256)
fused_kernel(const float* __restrict__ enc,
             const float* __restrict__ pitch,
             const float* __restrict__ energy,
             const float* __restrict__ dur,
             const float* __restrict__ ptab,
             const float* __restrict__ etab,
             float* __restrict__ out) {
    int tid = threadIdx.x;
    int wl  = tid & 31;            // lane: owns floats [wl*8, wl*8+8) of H row
    int w   = tid >> 5;            // warp 0..7

    if (blockIdx.x < NTB) {
        int b    = blockIdx.x >> 6;          // 64 token-blocks per batch
        int tb   = blockIdx.x & 63;
        int tok  = tb * TPB + w;             // local token index in [0,512)
        int row  = b * SS + tok;

        // ---- issue scan-independent loads early ----
        const float4* e4 = (const float4*)(enc + (size_t)row * HH) + wl * 2;
        float4 a0 = e4[0], a1 = e4[1];
        float pv = __ldg(pitch  + row);
        float ev = __ldg(energy + row);

        // ---- local block scan of this batch's 512 durations ----
        __shared__ int s_cum[SS];
        __shared__ int s_wt[8];
        int d0 = clamped_dur(dur, b * SS + 2 * tid);
        int d1 = clamped_dur(dur, b * SS + 2 * tid + 1);
        int v = d0 + d1;                      // pair sum
        #pragma unroll
        for (int off = 1; off < 32; off <<= 1) {
            int u = __shfl_up_sync(0xffffffffu, v, off);
            if (wl >= off) v += u;
        }
        if (wl == 31) s_wt[w] = v;
        __syncthreads();
        if (w == 0) {
            int t = (wl < 8) ? s_wt[wl] : 0;
            #pragma unroll
            for (int off = 1; off < 8; off <<= 1) {
                int u = __shfl_up_sync(0xffffffffu, t, off);
                if (wl >= off) t += u;
            }
            if (wl < 8) s_wt[wl] = t;
        }
        __syncthreads();
        int incl = ((w > 0) ? s_wt[w - 1] : 0) + v;   // cum through 2*tid+1
        s_cum[2 * tid]     = incl - d1;
        s_cum[2 * tid + 1] = incl;

        // ---- bins + table rows while scan settles ----
        int pb = quantize_bin(pv, 50.0f, 400.0f);
        int eb = quantize_bin(ev,  0.0f,   1.0f);

        const float4* p4 = (const float4*)(ptab + (size_t)pb * HH) + wl * 2;
        const float4* q4 = (const float4*)(etab + (size_t)eb * HH) + wl * 2;
        float4 p0 = p4[0], p1 = p4[1];
        float4 q0 = q4[0], q1 = q4[1];

        float4 r0, r1;
        r0.x = a0.x + p0.x + q0.x;  r0.y = a0.y + p0.y + q0.y;
        r0.z = a0.z + p0.z + q0.z;  r0.w = a0.w + p0.w + q0.w;
        r1.x = a1.x + p1.x + q1.x;  r1.y = a1.y + p1.y + q1.y;
        r1.z = a1.z + p1.z + q1.z;  r1.w = a1.w + p1.w + q1.w;

        __syncthreads();
        int start = (tok == 0) ? 0 : s_cum[tok - 1];
        int end   = s_cum[tok];

        // ---- scatter: one 256-bit streaming store per lane per frame ----
        float* base = out + (size_t)b * TT * HH + wl * 8;
        for (int t = start; t < end; ++t)
            stcs_v8(base + (size_t)t * HH, r0, r1);
    } else {
        int zid = blockIdx.x - NTB;            // [0, NZB)
        int b   = zid >> 7;                    // 128 chunks per batch (4096/32)
        int t0c = (zid & 127) * ZF;            // chunk start frame

        // all durations >= 1 => total >= SS; frames < SS never zeroed
        if (t0c + ZF <= SS) return;

        // ---- block reduction: total = sum of this batch's durations ----
        __shared__ int s_wt[8];
        int v = clamped_dur(dur, b * SS + 2 * tid)
              + clamped_dur(dur, b * SS + 2 * tid + 1);
        #pragma unroll
        for (int off = 16; off > 0; off >>= 1)
            v += __shfl_down_sync(0xffffffffu, v, off);
        if (wl == 0) s_wt[w] = v;
        __syncthreads();
        if (w == 0) {
            int t = (wl < 8) ? s_wt[wl] : 0;
            #pragma unroll
            for (int off = 4; off > 0; off >>= 1)
                t += __shfl_down_sync(0xffffffffu, t, off);
            if (wl == 0) s_wt[0] = t;
        }
        __syncthreads();
        int total = s_wt[0];

        int t0 = t0c + w * (ZF / TPB);         // 4 frames per warp
        if (t0 + ZF / TPB <= total) return;

        float4 z = make_float4(0.f, 0.f, 0.f, 0.f);
        float* base = out + ((size_t)b * TT + t0) * HH + wl * 8;
        #pragma unroll
        for (int f = 0; f < ZF / TPB; ++f) {
            if (t0 + f >= total)
                stcs_v8(base + (size_t)f * HH, z, z);
        }
    }
}

extern "C" void kernel_launch(void* const* d_in, const int* in_sizes, int n_in,
                              void* d_out, int out_size) {
    const float* enc    = (const float*)d_in[0];
    const float* pitch  = (const float*)d_in[1];
    const float* energy = (const float*)d_in[2];
    const float* dur    = (const float*)d_in[3];
    const float* ptab   = (const float*)d_in[4];
    const float* etab   = (const float*)d_in[5];
    float* out = (float*)d_out;

    fused_kernel<<<NTB + NZB, 256>>>(enc, pitch, energy, dur, ptab, etab, out);
}

// round 8
// speedup vs baseline: 1.0804x; 1.0804x over previous
#include <cuda_runtime.h>

#define BB 32
#define SS 512
#define HH 256
#define NB 256
#define TT 4096   // MAX_LEN

#define NTOK   (BB * SS)        // 16384 tokens
#define TOKG   2                // tokens per 64-lane group
#define GROUPS 4                // groups per 256-thread block
#define TPB    (TOKG * GROUPS)  // 8 tokens per block
#define NTB    (NTOK / TPB)     // 2048 token blocks (64 per batch)

#define ZF     32               // frames per zerofill block (4 groups x 8)
#define NZB    (BB * (TT / ZF)) // 4096 zerofill blocks

// searchsorted(linspace(vmin,vmax,NB), v, side='left'), clip [0, NB-1].
// Post-clip v <= b[NB-1] so answer in [0, NB-1]: 8 exact iterations.
__device__ __forceinline__ int quantize_bin(float v, float vmin, float vmax) {
    v = fminf(fmaxf(v, vmin), vmax);
    float step = __fdiv_rn(__fsub_rn(vmax, vmin), (float)(NB - 1));
    int lo = 0, hi = NB - 1;
    #pragma unroll
    for (int it = 0; it < 8; ++it) {
        int mid = (lo + hi) >> 1;
        float b = __fadd_rn(__fmul_rn((float)mid, step), vmin);
        if (b >= v) hi = mid; else lo = mid + 1;
    }
    return lo;
}

__device__ __forceinline__ int clamped_dur(const float* __restrict__ dur, int i) {
    return max((int)rintf(__ldg(dur + i)), 1);   // jnp.round = half-to-even
}

// Single fused kernel, 256 threads/block (R6 structure).
//   blockIdx.x <  NTB : 8 tokens of one batch; local block scan of the
//                       batch's duration row, then .cs streaming scatter.
//   blockIdx.x >= NTB : 32 frames; zero tail with DEFAULT (write-back)
//                       stores so repeated identical writes coalesce in L2
//                       across graph replays instead of draining to DRAM.
__global__ void __launch_bounds__(256)
fused_kernel(const float* __restrict__ enc,
             const float* __restrict__ pitch,
             const float* __restrict__ energy,
             const float* __restrict__ dur,
             const float* __restrict__ ptab,
             const float* __restrict__ etab,
             float* __restrict__ out) {
    int tid  = threadIdx.x;
    int gid  = tid >> 6;           // 0..3
    int lane = tid & 63;           // float4 index within H row
    int wl   = tid & 31;
    int w    = tid >> 5;           // 8 warps

    if (blockIdx.x < NTB) {
        int b    = blockIdx.x >> 6;          // 64 token-blocks per batch
        int tb   = blockIdx.x & 63;
        int tok0 = tb * TPB + gid * TOKG;    // local token index in [0,512)
        int row0 = b * SS + tok0;
        int row1 = row0 + 1;

        // ---- issue scatter-independent loads early ----
        float4 a0 = ((const float4*)(enc + (size_t)row0 * HH))[lane];
        float4 a1 = ((const float4*)(enc + (size_t)row1 * HH))[lane];
        float pv0 = __ldg(pitch  + row0);
        float pv1 = __ldg(pitch  + row1);
        float ev0 = __ldg(energy + row0);
        float ev1 = __ldg(energy + row1);

        // ---- local block scan of this batch's 512 durations ----
        __shared__ int s_cum[SS];
        __shared__ int s_wt[8];
        int d0 = clamped_dur(dur, b * SS + 2 * tid);
        int d1 = clamped_dur(dur, b * SS + 2 * tid + 1);
        int v = d0 + d1;                      // pair sum
        #pragma unroll
        for (int off = 1; off < 32; off <<= 1) {
            int u = __shfl_up_sync(0xffffffffu, v, off);
            if (wl >= off) v += u;
        }
        if (wl == 31) s_wt[w] = v;
        __syncthreads();
        if (w == 0) {
            int t = (wl < 8) ? s_wt[wl] : 0;
            #pragma unroll
            for (int off = 1; off < 8; off <<= 1) {
                int u = __shfl_up_sync(0xffffffffu, t, off);
                if (wl >= off) t += u;
            }
            if (wl < 8) s_wt[wl] = t;
        }
        __syncthreads();
        int incl = ((w > 0) ? s_wt[w - 1] : 0) + v;   // cum through 2*tid+1
        s_cum[2 * tid]     = incl - d1;
        s_cum[2 * tid + 1] = incl;

        // ---- bins + table rows while scan settles ----
        int pb0 = quantize_bin(pv0, 50.0f, 400.0f);
        int pb1 = quantize_bin(pv1, 50.0f, 400.0f);
        int eb0 = quantize_bin(ev0,  0.0f,   1.0f);
        int eb1 = quantize_bin(ev1,  0.0f,   1.0f);

        float4 p0 = ((const float4*)(ptab + (size_t)pb0 * HH))[lane];
        float4 p1 = ((const float4*)(ptab + (size_t)pb1 * HH))[lane];
        float4 q0 = ((const float4*)(etab + (size_t)eb0 * HH))[lane];
        float4 q1 = ((const float4*)(etab + (size_t)eb1 * HH))[lane];

        float4 r0, r1;
        r0.x = a0.x + p0.x + q0.x;  r0.y = a0.y + p0.y + q0.y;
        r0.z = a0.z + p0.z + q0.z;  r0.w = a0.w + p0.w + q0.w;
        r1.x = a1.x + p1.x + q1.x;  r1.y = a1.y + p1.y + q1.y;
        r1.z = a1.z + p1.z + q1.z;  r1.w = a1.w + p1.w + q1.w;

        __syncthreads();
        int start = (tok0 == 0) ? 0 : s_cum[tok0 - 1];
        int c0    = s_cum[tok0];
        int c1    = s_cum[tok0 + 1];

        // ---- scatter (streaming .cs: data differs each replay, evict early) ----
        size_t fbase = (size_t)b * TT * (HH / 4) + lane;
        float4* o4 = (float4*)out;
        for (int t = start; t < c0; ++t)
            __stcs(o4 + fbase + (size_t)t * (HH / 4), r0);
        for (int t = c0; t < c1; ++t)
            __stcs(o4 + fbase + (size_t)t * (HH / 4), r1);
    } else {
        int zid = blockIdx.x - NTB;            // [0, NZB)
        int b   = zid >> 7;                    // 128 chunks per batch (4096/32)
        int t0c = (zid & 127) * ZF;            // chunk start frame

        // all durations >= 1 => total >= SS; frames < SS are never zero
        if (t0c + ZF <= SS) return;

        // ---- block reduction: total = sum of this batch's durations ----
        __shared__ int s_wt[8];
        int v = clamped_dur(dur, b * SS + 2 * tid)
              + clamped_dur(dur, b * SS + 2 * tid + 1);
        #pragma unroll
        for (int off = 16; off > 0; off >>= 1)
            v += __shfl_down_sync(0xffffffffu, v, off);
        if (wl == 0) s_wt[w] = v;
        __syncthreads();
        if (w == 0) {
            int t = (wl < 8) ? s_wt[wl] : 0;
            #pragma unroll
            for (int off = 4; off > 0; off >>= 1)
                t += __shfl_down_sync(0xffffffffu, t, off);
            if (wl == 0) s_wt[0] = t;
        }
        __syncthreads();
        int total = s_wt[0];

        int t0 = t0c + gid * (ZF / GROUPS);
        if (t0 + ZF / GROUPS <= total) return;

        // DEFAULT stores (write-back, allocate): identical zeros each replay
        // can stay dirty-resident in L2 and never re-drain to DRAM.
        float4 z = make_float4(0.f, 0.f, 0.f, 0.f);
        float4* base = (float4*)out + ((size_t)b * TT + t0) * (HH / 4) + lane;
        #pragma unroll
        for (int f = 0; f < ZF / GROUPS; ++f) {
            if (t0 + f >= total)
                base[f * (HH / 4)] = z;
        }
    }
}

extern "C" void kernel_launch(void* const* d_in, const int* in_sizes, int n_in,
                              void* d_out, int out_size) {
    const float* enc    = (const float*)d_in[0];
    const float* pitch  = (const float*)d_in[1];
    const float* energy = (const float*)d_in[2];
    const float* dur    = (const float*)d_in[3];
    const float* ptab   = (const float*)d_in[4];
    const float* etab   = (const float*)d_in[5];
    float* out = (float*)d_out;

    fused_kernel<<<NTB + NZB, 256>>>(enc, pitch, energy, dur, ptab, etab, out);
}